// round 1
// baseline (speedup 1.0000x reference)
#include <cuda_runtime.h>

#define FLT_MAX_ 3.402823466e38f

// Scratch (64 MB) — __device__ globals per allocation rules.
__device__ float g_Q[4096 * 1024];
__device__ float g_K[4096 * 1024];
__device__ float g_V[4096 * 1024];
__device__ float g_C[4096 * 1024];

// ---------------------------------------------------------------------------
// SGEMM: C[M,N] = A[M,K] @ B[K,N], row-major, M%128==0, N%128==0, K%8==0.
// 128x128 block tile, BK=8, 256 threads, 8x8 micro-tile.
// ---------------------------------------------------------------------------
__global__ __launch_bounds__(256)
void sgemm128(const float* __restrict__ A, const float* __restrict__ Bm,
              float* __restrict__ C, int M, int N, int K) {
    __shared__ float As[8][128];   // As[k][m] (transposed)
    __shared__ float Bs[8][128];   // Bs[k][n]

    const int tid = threadIdx.x;
    const int bm = blockIdx.y * 128;
    const int bn = blockIdx.x * 128;

    const int a_row = tid >> 1;          // 0..127
    const int a_k4  = (tid & 1) * 4;     // 0 or 4
    const int b_k   = tid >> 5;          // 0..7
    const int b_n4  = (tid & 31) * 4;    // 0..124

    const int ty = tid >> 4, tx = tid & 15;

    const float* Ap = A + (size_t)(bm + a_row) * K + a_k4;
    const float* Bp = Bm + (size_t)b_k * N + bn + b_n4;

    float acc[8][8];
    #pragma unroll
    for (int i = 0; i < 8; i++)
        #pragma unroll
        for (int j = 0; j < 8; j++) acc[i][j] = 0.f;

    for (int k0 = 0; k0 < K; k0 += 8) {
        float4 av = *(const float4*)(Ap + k0);
        float4 bv = *(const float4*)(Bp + (size_t)k0 * N);
        As[a_k4 + 0][a_row] = av.x;
        As[a_k4 + 1][a_row] = av.y;
        As[a_k4 + 2][a_row] = av.z;
        As[a_k4 + 3][a_row] = av.w;
        *(float4*)&Bs[b_k][b_n4] = bv;
        __syncthreads();

        #pragma unroll
        for (int kk = 0; kk < 8; kk++) {
            float a[8], b[8];
            *(float4*)&a[0] = *(const float4*)&As[kk][ty * 8];
            *(float4*)&a[4] = *(const float4*)&As[kk][ty * 8 + 4];
            *(float4*)&b[0] = *(const float4*)&Bs[kk][tx * 8];
            *(float4*)&b[4] = *(const float4*)&Bs[kk][tx * 8 + 4];
            #pragma unroll
            for (int i = 0; i < 8; i++)
                #pragma unroll
                for (int j = 0; j < 8; j++)
                    acc[i][j] = fmaf(a[i], b[j], acc[i][j]);
        }
        __syncthreads();
    }

    #pragma unroll
    for (int i = 0; i < 8; i++) {
        float* Cp = C + (size_t)(bm + ty * 8 + i) * N + bn + tx * 8;
        *(float4*)Cp       = make_float4(acc[i][0], acc[i][1], acc[i][2], acc[i][3]);
        *(float4*)(Cp + 4) = make_float4(acc[i][4], acc[i][5], acc[i][6], acc[i][7]);
    }
}

// ---------------------------------------------------------------------------
// Flash attention: per block = one (batch, head, 64-row q tile).
// Q/K/V layout [b*2048+s][head*64+d] (GEMM output). 64-wide KV tiles,
// online softmax, P staged through padded smem for the PV mini-GEMM.
// ---------------------------------------------------------------------------
__global__ __launch_bounds__(256)
void attn64(const float* __restrict__ Q, const float* __restrict__ K,
            const float* __restrict__ V, const int* __restrict__ mask,
            float* __restrict__ O) {
    extern __shared__ float sm[];
    float* Qs = sm;               // [64][64] : Qs[d*64+q]  (transposed)
    float* Ks = sm + 4096;        // [64][64] : Ks[d*64+k]  (transposed)
    float* Vs = sm + 8192;        // [64][64] : Vs[k*64+d]  (natural)
    float* Ps = sm + 12288;       // [64][65] : Ps[k*65+q]  (padded)
    int*  msk = (int*)(sm + 12288 + 4160);  // [64]

    const int qb = blockIdx.x, head = blockIdx.y, b = blockIdx.z;
    const int tid = threadIdx.x;
    const int ty = tid >> 4, tx = tid & 15;
    const int q0 = qb * 64;

    const float* Qg = Q + ((size_t)b * 2048 + q0) * 1024 + head * 64;
    const float* Kg = K + (size_t)b * 2048 * 1024 + head * 64;
    const float* Vg = V + (size_t)b * 2048 * 1024 + head * 64;

    // Loader mapping: 16 distinct rows per warp -> 2-way smem write conflicts,
    // 32B-contiguous global sectors.
    const int lp = tid >> 1, lh = tid & 1;
    const int lr = lp & 63;        // row within 64-row tile
    const int lc = lp >> 6;        // 0/1

    // Load Q tile (transposed)
    #pragma unroll
    for (int i = 0; i < 4; i++) {
        int d4 = lc * 8 + lh * 4 + i * 16;
        float4 v = *(const float4*)(Qg + (size_t)lr * 1024 + d4);
        Qs[(d4 + 0) * 64 + lr] = v.x;
        Qs[(d4 + 1) * 64 + lr] = v.y;
        Qs[(d4 + 2) * 64 + lr] = v.z;
        Qs[(d4 + 3) * 64 + lr] = v.w;
    }

    float m_run[4], l_run[4], o[4][4];
    #pragma unroll
    for (int i = 0; i < 4; i++) {
        m_run[i] = -FLT_MAX_;
        l_run[i] = 0.f;
        #pragma unroll
        for (int j = 0; j < 4; j++) o[i][j] = 0.f;
    }

    for (int kt = 0; kt < 32; kt++) {
        const int k0 = kt * 64;

        // Load K (transposed) and V (natural) tiles + mask
        #pragma unroll
        for (int i = 0; i < 4; i++) {
            int d4 = lc * 8 + lh * 4 + i * 16;
            float4 kv = *(const float4*)(Kg + (size_t)(k0 + lr) * 1024 + d4);
            Ks[(d4 + 0) * 64 + lr] = kv.x;
            Ks[(d4 + 1) * 64 + lr] = kv.y;
            Ks[(d4 + 2) * 64 + lr] = kv.z;
            Ks[(d4 + 3) * 64 + lr] = kv.w;
            float4 vv = *(const float4*)(Vg + (size_t)(k0 + lr) * 1024 + d4);
            *(float4*)(Vs + lr * 64 + d4) = vv;
        }
        if (tid < 64) msk[tid] = mask[b * 2048 + k0 + tid];
        __syncthreads();

        // S = Q @ K^T  (64x64x64 mini-GEMM, 4x4 micro-tile)
        float s[4][4];
        #pragma unroll
        for (int i = 0; i < 4; i++)
            #pragma unroll
            for (int j = 0; j < 4; j++) s[i][j] = 0.f;

        #pragma unroll 4
        for (int d = 0; d < 64; d++) {
            float4 av = *(const float4*)(Qs + d * 64 + 4 * ty);
            float4 bv = *(const float4*)(Ks + d * 64 + 4 * tx);
            float a[4] = {av.x, av.y, av.z, av.w};
            float bb[4] = {bv.x, bv.y, bv.z, bv.w};
            #pragma unroll
            for (int i = 0; i < 4; i++)
                #pragma unroll
                for (int j = 0; j < 4; j++)
                    s[i][j] = fmaf(a[i], bb[j], s[i][j]);
        }

        // scale -> clip -> mask (reference order)
        int mj[4];
        #pragma unroll
        for (int j = 0; j < 4; j++) mj[j] = msk[4 * tx + j];
        #pragma unroll
        for (int i = 0; i < 4; i++)
            #pragma unroll
            for (int j = 0; j < 4; j++) {
                float v = s[i][j] * 0.125f;
                v = fminf(fmaxf(v, -10000.f), 10000.f);
                s[i][j] = mj[j] ? v : -FLT_MAX_;
            }

        // Online softmax: row reductions across the 16-lane tx group
        #pragma unroll
        for (int i = 0; i < 4; i++) {
            float mt = fmaxf(fmaxf(s[i][0], s[i][1]), fmaxf(s[i][2], s[i][3]));
            #pragma unroll
            for (int off = 8; off > 0; off >>= 1)
                mt = fmaxf(mt, __shfl_xor_sync(0xffffffffu, mt, off, 16));
            float mnew = fmaxf(m_run[i], mt);
            float alpha = __expf(m_run[i] - mnew);   // -FLT_MAX - finite -> 0
            float rs = 0.f;
            #pragma unroll
            for (int j = 0; j < 4; j++) {
                float p = __expf(s[i][j] - mnew);
                s[i][j] = p;
                rs += p;
            }
            #pragma unroll
            for (int off = 8; off > 0; off >>= 1)
                rs += __shfl_xor_sync(0xffffffffu, rs, off, 16);
            m_run[i] = mnew;
            l_run[i] = l_run[i] * alpha + rs;
            #pragma unroll
            for (int j = 0; j < 4; j++) o[i][j] *= alpha;
        }

        // Stage P (transposed, padded) for the PV mini-GEMM
        #pragma unroll
        for (int i = 0; i < 4; i++)
            #pragma unroll
            for (int j = 0; j < 4; j++)
                Ps[(4 * tx + j) * 65 + 4 * ty + i] = s[i][j];
        __syncthreads();

        // O += P @ V
        #pragma unroll 4
        for (int k = 0; k < 64; k++) {
            float a[4];
            #pragma unroll
            for (int i = 0; i < 4; i++) a[i] = Ps[k * 65 + 4 * ty + i];
            float4 bv = *(const float4*)(Vs + k * 64 + 4 * tx);
            float bb[4] = {bv.x, bv.y, bv.z, bv.w};
            #pragma unroll
            for (int i = 0; i < 4; i++)
                #pragma unroll
                for (int j = 0; j < 4; j++)
                    o[i][j] = fmaf(a[i], bb[j], o[i][j]);
        }
        __syncthreads();
    }

    // Normalize and write context [b,s,h]
    float* Og = O + ((size_t)b * 2048 + q0) * 1024 + head * 64;
    #pragma unroll
    for (int i = 0; i < 4; i++) {
        float inv = 1.f / l_run[i];
        float4 v = make_float4(o[i][0] * inv, o[i][1] * inv,
                               o[i][2] * inv, o[i][3] * inv);
        *(float4*)(Og + (size_t)(4 * ty + i) * 1024 + 4 * tx) = v;
    }
}

// ---------------------------------------------------------------------------
// Launch: X@W_Q, X@W_K, X@W_V -> attention -> ctx@W_O
// Inputs (metadata order): X, mask, W_Q, W_K, W_V, W_O
// ---------------------------------------------------------------------------
extern "C" void kernel_launch(void* const* d_in, const int* in_sizes, int n_in,
                              void* d_out, int out_size) {
    const float* X    = (const float*)d_in[0];
    const int*   mask = (const int*)d_in[1];
    const float* W_Q  = (const float*)d_in[2];
    const float* W_K  = (const float*)d_in[3];
    const float* W_V  = (const float*)d_in[4];
    const float* W_O  = (const float*)d_in[5];
    float* out = (float*)d_out;

    float *q, *k, *v, *c;
    cudaGetSymbolAddress((void**)&q, g_Q);
    cudaGetSymbolAddress((void**)&k, g_K);
    cudaGetSymbolAddress((void**)&v, g_V);
    cudaGetSymbolAddress((void**)&c, g_C);

    dim3 gg(1024 / 128, 4096 / 128);
    sgemm128<<<gg, 256>>>(X, W_Q, q, 4096, 1024, 1024);
    sgemm128<<<gg, 256>>>(X, W_K, k, 4096, 1024, 1024);
    sgemm128<<<gg, 256>>>(X, W_V, v, 4096, 1024, 1024);

    const int smem_bytes = (4096 * 3 + 64 * 65) * 4 + 64 * 4;  // 66048
    cudaFuncSetAttribute(attn64, cudaFuncAttributeMaxDynamicSharedMemorySize,
                         smem_bytes);
    dim3 ga(32, 16, 2);
    attn64<<<ga, 256, smem_bytes>>>(q, k, v, mask, c);

    sgemm128<<<gg, 256>>>(c, W_O, out, 4096, 1024, 1024);
}

// round 3
// speedup vs baseline: 1.4626x; 1.4626x over previous
#include <cuda_runtime.h>
#include <cuda_bf16.h>
#include <cstdint>

#define FLT_MAX_ 3.402823466e38f

// ---------------- scratch (device globals; no allocs allowed) ---------------
__device__ float g_Q[4096 * 1024];
__device__ float g_K[4096 * 1024];
__device__ float g_V[4096 * 1024];
__device__ float g_C[4096 * 1024];
__device__ __nv_bfloat16 g_Ahi[4096 * 1024];
__device__ __nv_bfloat16 g_Alo[4096 * 1024];
__device__ __nv_bfloat16 g_WThi[1024 * 1024];
__device__ __nv_bfloat16 g_WTlo[1024 * 1024];

// ---------------- helpers (non-'a' features only: sm_80-era PTX) ------------
__device__ __forceinline__ uint32_t smem_u32(const void* p) {
    uint32_t a;
    asm("{ .reg .u64 t; cvta.to.shared.u64 t, %1; cvt.u32.u64 %0, t; }"
        : "=r"(a) : "l"(p));
    return a;
}
__device__ __forceinline__ uint32_t sw128(uint32_t off) {
    return off ^ ((off >> 3) & 0x70);
}
__device__ __forceinline__ void ldsm4(uint32_t* r, uint32_t addr) {
    asm volatile("ldmatrix.sync.aligned.m8n8.x4.shared.b16 {%0,%1,%2,%3}, [%4];"
                 : "=r"(r[0]), "=r"(r[1]), "=r"(r[2]), "=r"(r[3]) : "r"(addr));
}
__device__ __forceinline__ void mma16816(float* d, const uint32_t* a,
                                         const uint32_t* b) {
    asm volatile(
        "mma.sync.aligned.m16n8k16.row.col.f32.bf16.bf16.f32 "
        "{%0,%1,%2,%3}, {%4,%5,%6,%7}, {%8,%9}, {%0,%1,%2,%3};"
        : "+f"(d[0]), "+f"(d[1]), "+f"(d[2]), "+f"(d[3])
        : "r"(a[0]), "r"(a[1]), "r"(a[2]), "r"(a[3]), "r"(b[0]), "r"(b[1]));
}
__device__ __forceinline__ void cpasync16(uint32_t dst, const void* src) {
    asm volatile("cp.async.cg.shared.global [%0], [%1], 16;" :: "r"(dst), "l"(src));
}
#define CP_COMMIT() asm volatile("cp.async.commit_group;" ::: "memory")
#define CP_WAIT1() asm volatile("cp.async.wait_group 1;" ::: "memory")
#define CP_WAIT0() asm volatile("cp.async.wait_group 0;" ::: "memory")

// ---------------------------------------------------------------------------
// split fp32 -> bf16 hi/lo (same layout)
// ---------------------------------------------------------------------------
__global__ __launch_bounds__(256)
void split_rows(const float* __restrict__ src, __nv_bfloat16* __restrict__ hi,
                __nv_bfloat16* __restrict__ lo, int n4) {
    int i = blockIdx.x * 256 + threadIdx.x;
    if (i >= n4) return;
    float4 v = ((const float4*)src)[i];
    float x[4] = {v.x, v.y, v.z, v.w};
    __nv_bfloat16 h[4], l[4];
    #pragma unroll
    for (int j = 0; j < 4; j++) {
        h[j] = __float2bfloat16(x[j]);
        l[j] = __float2bfloat16(x[j] - __bfloat162float(h[j]));
    }
    ((__nv_bfloat162*)hi)[i * 2 + 0] = __nv_bfloat162(h[0], h[1]);
    ((__nv_bfloat162*)hi)[i * 2 + 1] = __nv_bfloat162(h[2], h[3]);
    ((__nv_bfloat162*)lo)[i * 2 + 0] = __nv_bfloat162(l[0], l[1]);
    ((__nv_bfloat162*)lo)[i * 2 + 1] = __nv_bfloat162(l[2], l[3]);
}

// ---------------------------------------------------------------------------
// transpose + split: W[1024(k)][1024(n)] fp32 -> WT[n][k] bf16 hi/lo
// ---------------------------------------------------------------------------
__global__ __launch_bounds__(256)
void transpose_split(const float* __restrict__ W, __nv_bfloat16* __restrict__ th,
                     __nv_bfloat16* __restrict__ tl) {
    __shared__ float s[32][33];
    const int n0 = blockIdx.x * 32, k0 = blockIdx.y * 32;
    const int tx = threadIdx.x, ty = threadIdx.y;  // 32 x 8
    #pragma unroll
    for (int i = 0; i < 4; i++)
        s[ty + 8 * i][tx] = W[(size_t)(k0 + ty + 8 * i) * 1024 + n0 + tx];
    __syncthreads();
    #pragma unroll
    for (int i = 0; i < 4; i++) {
        int n = ty + 8 * i;
        float v = s[tx][n];
        __nv_bfloat16 h = __float2bfloat16(v);
        __nv_bfloat16 l = __float2bfloat16(v - __bfloat162float(h));
        size_t o = (size_t)(n0 + n) * 1024 + k0 + tx;
        th[o] = h;
        tl[o] = l;
    }
}

// ---------------------------------------------------------------------------
// HMMA bf16x3 GEMM: C[4096,1024] = A[4096,1024] @ WT^T
//   A row-major bf16 hi/lo; WT [n][k] bf16 hi/lo (B col-major for mma row.col).
//   CTA 128x128, 8 warps (warp tile 64x32), KC=64, double-buffered cp.async,
//   SW128 smem + ldmatrix. 3 products: AhiBhi + AhiBlo + AloBhi.
// ---------------------------------------------------------------------------
#define GBUF 65536                    // per-buffer: Ahi16K | Alo16K | Bhi16K | Blo16K
#define GEMM_SMEM (2 * GBUF)          // 131072

__global__ __launch_bounds__(256, 1)
void gemm_hmma(const __nv_bfloat16* __restrict__ Ahi,
               const __nv_bfloat16* __restrict__ Alo,
               const __nv_bfloat16* __restrict__ Bhi,
               const __nv_bfloat16* __restrict__ Blo,
               float* __restrict__ C) {
    extern __shared__ char smem[];
    const uint32_t sb = smem_u32(smem);
    const int tid = threadIdx.x, wid = tid >> 5, lane = tid & 31;
    const int bn = blockIdx.x * 128, bm = blockIdx.y * 128;
    const int warp_m = (wid & 1) * 64, warp_n = (wid >> 1) * 32;

    const uint4* Asrc[2] = {(const uint4*)(Ahi + (size_t)bm * 1024),
                            (const uint4*)(Alo + (size_t)bm * 1024)};
    const uint4* Bsrc[2] = {(const uint4*)(Bhi + (size_t)bn * 1024),
                            (const uint4*)(Blo + (size_t)bn * 1024)};

    // loader: 16 granules (16B) per thread per chunk
    const int lrow = tid >> 3, lcol = tid & 7;   // granule (row, col) base
    const uint32_t ldst = sw128(lrow * 128 + lcol * 16);

    float acc[4][4][4];
    #pragma unroll
    for (int i = 0; i < 4; i++)
        #pragma unroll
        for (int j = 0; j < 4; j++)
            #pragma unroll
            for (int r = 0; r < 4; r++) acc[i][j][r] = 0.f;

    // fragment addresses (constant swizzled offsets per lane)
    const int arow = warp_m + (lane & 15);
    const int acb = (lane >> 4) << 4;                       // 0 or 16
    const int brow = warp_n + ((lane >> 4) & 1) * 8 + (lane & 7);
    const int bcb = ((lane >> 3) & 1) * 16;

    auto load_chunk = [&](int c) {
        const uint32_t base = sb + (c & 1) * GBUF;
        const int kc8 = c * 8;
        #pragma unroll
        for (int pr = 0; pr < 2; pr++) {
            #pragma unroll
            for (int p = 0; p < 4; p++)
                cpasync16(base + pr * 16384 + (ldst + p * 4096),
                          Asrc[pr] + (size_t)(lrow + p * 32) * 128 + kc8 + lcol);
        }
        #pragma unroll
        for (int pr = 0; pr < 2; pr++) {
            #pragma unroll
            for (int p = 0; p < 4; p++)
                cpasync16(base + 32768 + pr * 16384 + (ldst + p * 4096),
                          Bsrc[pr] + (size_t)(lrow + p * 32) * 128 + kc8 + lcol);
        }
        CP_COMMIT();
    };

    load_chunk(0);
    for (int c = 0; c < 16; c++) {
        if (c + 1 < 16) { load_chunk(c + 1); CP_WAIT1(); }
        else CP_WAIT0();
        __syncthreads();

        const uint32_t base = sb + (c & 1) * GBUF;
        #pragma unroll
        for (int k16 = 0; k16 < 4; k16++) {
            uint32_t a_hi[4][4], a_lo[4][4], b_hi[2][4], b_lo[2][4];
            const int acolb = k16 * 32 + acb;
            const int bcolb = k16 * 32 + bcb;
            #pragma unroll
            for (int mi = 0; mi < 4; mi++) {
                uint32_t off = (uint32_t)(arow + mi * 16) * 128 + acolb;
                ldsm4(a_hi[mi], base + sw128(off));
                ldsm4(a_lo[mi], base + 16384 + sw128(off));
            }
            #pragma unroll
            for (int nh = 0; nh < 2; nh++) {
                uint32_t off = (uint32_t)(brow + nh * 16) * 128 + bcolb;
                ldsm4(b_hi[nh], base + 32768 + sw128(off));
                ldsm4(b_lo[nh], base + 49152 + sw128(off));
            }
            #pragma unroll
            for (int mi = 0; mi < 4; mi++)
                #pragma unroll
                for (int ni = 0; ni < 4; ni++) {
                    const uint32_t* bh = &b_hi[ni >> 1][(ni & 1) * 2];
                    const uint32_t* bl = &b_lo[ni >> 1][(ni & 1) * 2];
                    mma16816(acc[mi][ni], a_hi[mi], bh);
                    mma16816(acc[mi][ni], a_hi[mi], bl);
                    mma16816(acc[mi][ni], a_lo[mi], bh);
                }
        }
        __syncthreads();
    }

    // epilogue
    #pragma unroll
    for (int mi = 0; mi < 4; mi++) {
        const int r0 = bm + warp_m + mi * 16 + (lane >> 2);
        #pragma unroll
        for (int ni = 0; ni < 4; ni++) {
            const int c0 = bn + warp_n + ni * 8 + (lane & 3) * 2;
            *(float2*)(C + (size_t)r0 * 1024 + c0) =
                make_float2(acc[mi][ni][0], acc[mi][ni][1]);
            *(float2*)(C + (size_t)(r0 + 8) * 1024 + c0) =
                make_float2(acc[mi][ni][2], acc[mi][ni][3]);
        }
    }
}

// ---------------------------------------------------------------------------
// Flash attention (unchanged SIMT, R1-validated)
// ---------------------------------------------------------------------------
__global__ __launch_bounds__(256)
void attn64(const float* __restrict__ Q, const float* __restrict__ K,
            const float* __restrict__ V, const int* __restrict__ mask,
            float* __restrict__ O) {
    extern __shared__ float sm[];
    float* Qs = sm;
    float* Ks = sm + 4096;
    float* Vs = sm + 8192;
    float* Ps = sm + 12288;
    int* msk = (int*)(sm + 12288 + 4160);

    const int qb = blockIdx.x, head = blockIdx.y, b = blockIdx.z;
    const int tid = threadIdx.x;
    const int ty = tid >> 4, tx = tid & 15;
    const int q0 = qb * 64;

    const float* Qg = Q + ((size_t)b * 2048 + q0) * 1024 + head * 64;
    const float* Kg = K + (size_t)b * 2048 * 1024 + head * 64;
    const float* Vg = V + (size_t)b * 2048 * 1024 + head * 64;

    const int lp = tid >> 1, lh = tid & 1;
    const int lr = lp & 63;
    const int lc = lp >> 6;

    #pragma unroll
    for (int i = 0; i < 4; i++) {
        int d4 = lc * 8 + lh * 4 + i * 16;
        float4 v = *(const float4*)(Qg + (size_t)lr * 1024 + d4);
        Qs[(d4 + 0) * 64 + lr] = v.x;
        Qs[(d4 + 1) * 64 + lr] = v.y;
        Qs[(d4 + 2) * 64 + lr] = v.z;
        Qs[(d4 + 3) * 64 + lr] = v.w;
    }

    float m_run[4], l_run[4], o[4][4];
    #pragma unroll
    for (int i = 0; i < 4; i++) {
        m_run[i] = -FLT_MAX_;
        l_run[i] = 0.f;
        #pragma unroll
        for (int j = 0; j < 4; j++) o[i][j] = 0.f;
    }

    for (int kt = 0; kt < 32; kt++) {
        const int k0 = kt * 64;
        #pragma unroll
        for (int i = 0; i < 4; i++) {
            int d4 = lc * 8 + lh * 4 + i * 16;
            float4 kv = *(const float4*)(Kg + (size_t)(k0 + lr) * 1024 + d4);
            Ks[(d4 + 0) * 64 + lr] = kv.x;
            Ks[(d4 + 1) * 64 + lr] = kv.y;
            Ks[(d4 + 2) * 64 + lr] = kv.z;
            Ks[(d4 + 3) * 64 + lr] = kv.w;
            float4 vv = *(const float4*)(Vg + (size_t)(k0 + lr) * 1024 + d4);
            *(float4*)(Vs + lr * 64 + d4) = vv;
        }
        if (tid < 64) msk[tid] = mask[b * 2048 + k0 + tid];
        __syncthreads();

        float s[4][4];
        #pragma unroll
        for (int i = 0; i < 4; i++)
            #pragma unroll
            for (int j = 0; j < 4; j++) s[i][j] = 0.f;

        #pragma unroll 4
        for (int d = 0; d < 64; d++) {
            float4 av = *(const float4*)(Qs + d * 64 + 4 * ty);
            float4 bv = *(const float4*)(Ks + d * 64 + 4 * tx);
            float a[4] = {av.x, av.y, av.z, av.w};
            float bb[4] = {bv.x, bv.y, bv.z, bv.w};
            #pragma unroll
            for (int i = 0; i < 4; i++)
                #pragma unroll
                for (int j = 0; j < 4; j++)
                    s[i][j] = fmaf(a[i], bb[j], s[i][j]);
        }

        int mj[4];
        #pragma unroll
        for (int j = 0; j < 4; j++) mj[j] = msk[4 * tx + j];
        #pragma unroll
        for (int i = 0; i < 4; i++)
            #pragma unroll
            for (int j = 0; j < 4; j++) {
                float v = s[i][j] * 0.125f;
                v = fminf(fmaxf(v, -10000.f), 10000.f);
                s[i][j] = mj[j] ? v : -FLT_MAX_;
            }

        #pragma unroll
        for (int i = 0; i < 4; i++) {
            float mt = fmaxf(fmaxf(s[i][0], s[i][1]), fmaxf(s[i][2], s[i][3]));
            #pragma unroll
            for (int off = 8; off > 0; off >>= 1)
                mt = fmaxf(mt, __shfl_xor_sync(0xffffffffu, mt, off, 16));
            float mnew = fmaxf(m_run[i], mt);
            float alpha = __expf(m_run[i] - mnew);
            float rs = 0.f;
            #pragma unroll
            for (int j = 0; j < 4; j++) {
                float p = __expf(s[i][j] - mnew);
                s[i][j] = p;
                rs += p;
            }
            #pragma unroll
            for (int off = 8; off > 0; off >>= 1)
                rs += __shfl_xor_sync(0xffffffffu, rs, off, 16);
            m_run[i] = mnew;
            l_run[i] = l_run[i] * alpha + rs;
            #pragma unroll
            for (int j = 0; j < 4; j++) o[i][j] *= alpha;
        }

        #pragma unroll
        for (int i = 0; i < 4; i++)
            #pragma unroll
            for (int j = 0; j < 4; j++)
                Ps[(4 * tx + j) * 65 + 4 * ty + i] = s[i][j];
        __syncthreads();

        #pragma unroll 4
        for (int k = 0; k < 64; k++) {
            float a[4];
            #pragma unroll
            for (int i = 0; i < 4; i++) a[i] = Ps[k * 65 + 4 * ty + i];
            float4 bv = *(const float4*)(Vs + k * 64 + 4 * tx);
            float bb[4] = {bv.x, bv.y, bv.z, bv.w};
            #pragma unroll
            for (int i = 0; i < 4; i++)
                #pragma unroll
                for (int j = 0; j < 4; j++)
                    o[i][j] = fmaf(a[i], bb[j], o[i][j]);
        }
        __syncthreads();
    }

    float* Og = O + ((size_t)b * 2048 + q0) * 1024 + head * 64;
    #pragma unroll
    for (int i = 0; i < 4; i++) {
        float inv = 1.f / l_run[i];
        float4 v = make_float4(o[i][0] * inv, o[i][1] * inv,
                               o[i][2] * inv, o[i][3] * inv);
        *(float4*)(Og + (size_t)(4 * ty + i) * 1024 + 4 * tx) = v;
    }
}

// ---------------------------------------------------------------------------
extern "C" void kernel_launch(void* const* d_in, const int* in_sizes, int n_in,
                              void* d_out, int out_size) {
    const float* X    = (const float*)d_in[0];
    const int*   mask = (const int*)d_in[1];
    const float* W_Q  = (const float*)d_in[2];
    const float* W_K  = (const float*)d_in[3];
    const float* W_V  = (const float*)d_in[4];
    const float* W_O  = (const float*)d_in[5];
    float* out = (float*)d_out;

    float *q, *k, *v, *c;
    __nv_bfloat16 *ahi, *alo, *wth, *wtl;
    cudaGetSymbolAddress((void**)&q, g_Q);
    cudaGetSymbolAddress((void**)&k, g_K);
    cudaGetSymbolAddress((void**)&v, g_V);
    cudaGetSymbolAddress((void**)&c, g_C);
    cudaGetSymbolAddress((void**)&ahi, g_Ahi);
    cudaGetSymbolAddress((void**)&alo, g_Alo);
    cudaGetSymbolAddress((void**)&wth, g_WThi);
    cudaGetSymbolAddress((void**)&wtl, g_WTlo);

    cudaFuncSetAttribute(gemm_hmma, cudaFuncAttributeMaxDynamicSharedMemorySize,
                         GEMM_SMEM);

    const int n4 = 4096 * 1024 / 4;
    dim3 gt(32, 32), bt(32, 8);
    dim3 gg(1024 / 128, 4096 / 128);

    // X -> hi/lo
    split_rows<<<n4 / 256, 256>>>(X, ahi, alo, n4);

    // Q/K/V projections
    transpose_split<<<gt, bt>>>(W_Q, wth, wtl);
    gemm_hmma<<<gg, 256, GEMM_SMEM>>>(ahi, alo, wth, wtl, q);
    transpose_split<<<gt, bt>>>(W_K, wth, wtl);
    gemm_hmma<<<gg, 256, GEMM_SMEM>>>(ahi, alo, wth, wtl, k);
    transpose_split<<<gt, bt>>>(W_V, wth, wtl);
    gemm_hmma<<<gg, 256, GEMM_SMEM>>>(ahi, alo, wth, wtl, v);

    // attention (SIMT)
    const int attn_smem = (4096 * 3 + 64 * 65) * 4 + 64 * 4;
    cudaFuncSetAttribute(attn64, cudaFuncAttributeMaxDynamicSharedMemorySize,
                         attn_smem);
    dim3 ga(32, 16, 2);
    attn64<<<ga, 256, attn_smem>>>(q, k, v, mask, c);

    // output projection
    split_rows<<<n4 / 256, 256>>>(c, ahi, alo, n4);
    transpose_split<<<gt, bt>>>(W_O, wth, wtl);
    gemm_hmma<<<gg, 256, GEMM_SMEM>>>(ahi, alo, wth, wtl, out);
}

// round 4
// speedup vs baseline: 3.1893x; 2.1805x over previous
#include <cuda_runtime.h>
#include <cuda_bf16.h>
#include <cstdint>

#define FLT_MAX_ 3.402823466e38f

// ---------------- scratch (device globals; no allocs allowed) ---------------
__device__ __nv_bfloat16 g_Ahi[4096 * 1024];   // X split, later ctx split
__device__ __nv_bfloat16 g_Alo[4096 * 1024];
__device__ __nv_bfloat16 g_WThi[1024 * 1024];
__device__ __nv_bfloat16 g_WTlo[1024 * 1024];
__device__ __nv_bfloat16 g_Qhi[4096 * 1024];
__device__ __nv_bfloat16 g_Qlo[4096 * 1024];
__device__ __nv_bfloat16 g_Khi[4096 * 1024];
__device__ __nv_bfloat16 g_Klo[4096 * 1024];
__device__ __nv_bfloat16 g_Vhi[4096 * 1024];
__device__ __nv_bfloat16 g_Vlo[4096 * 1024];

// ---------------- helpers (sm_80-era PTX only; no 'a' features) -------------
__device__ __forceinline__ uint32_t smem_u32(const void* p) {
    uint32_t a;
    asm("{ .reg .u64 t; cvta.to.shared.u64 t, %1; cvt.u32.u64 %0, t; }"
        : "=r"(a) : "l"(p));
    return a;
}
__device__ __forceinline__ uint32_t sw128(uint32_t off) {
    return off ^ ((off >> 3) & 0x70);
}
__device__ __forceinline__ void ldsm4(uint32_t* r, uint32_t addr) {
    asm volatile("ldmatrix.sync.aligned.m8n8.x4.shared.b16 {%0,%1,%2,%3}, [%4];"
                 : "=r"(r[0]), "=r"(r[1]), "=r"(r[2]), "=r"(r[3]) : "r"(addr));
}
__device__ __forceinline__ void ldsm4t(uint32_t* r, uint32_t addr) {
    asm volatile("ldmatrix.sync.aligned.m8n8.x4.trans.shared.b16 {%0,%1,%2,%3}, [%4];"
                 : "=r"(r[0]), "=r"(r[1]), "=r"(r[2]), "=r"(r[3]) : "r"(addr));
}
__device__ __forceinline__ void mma16816(float* d, const uint32_t* a,
                                         const uint32_t* b) {
    asm volatile(
        "mma.sync.aligned.m16n8k16.row.col.f32.bf16.bf16.f32 "
        "{%0,%1,%2,%3}, {%4,%5,%6,%7}, {%8,%9}, {%0,%1,%2,%3};"
        : "+f"(d[0]), "+f"(d[1]), "+f"(d[2]), "+f"(d[3])
        : "r"(a[0]), "r"(a[1]), "r"(a[2]), "r"(a[3]), "r"(b[0]), "r"(b[1]));
}
__device__ __forceinline__ void cpasync16(uint32_t dst, const void* src) {
    asm volatile("cp.async.cg.shared.global [%0], [%1], 16;" :: "r"(dst), "l"(src));
}
#define CP_COMMIT() asm volatile("cp.async.commit_group;" ::: "memory")
#define CP_WAIT1() asm volatile("cp.async.wait_group 1;" ::: "memory")
#define CP_WAIT0() asm volatile("cp.async.wait_group 0;" ::: "memory")

// pack two f32 into bf16x2 (x0 low half, x1 high half) + residual pair
__device__ __forceinline__ uint32_t packbf2(float lo, float hi) {
    uint32_t r;
    asm("cvt.rn.bf16x2.f32 %0, %1, %2;" : "=r"(r) : "f"(hi), "f"(lo));
    return r;
}
__device__ __forceinline__ void split2(float x0, float x1, uint32_t& hi,
                                       uint32_t& lo) {
    hi = packbf2(x0, x1);
    float h0 = __uint_as_float(hi << 16);
    float h1 = __uint_as_float(hi & 0xffff0000u);
    lo = packbf2(x0 - h0, x1 - h1);
}

// ---------------------------------------------------------------------------
// split fp32 -> bf16 hi/lo (same layout)
// ---------------------------------------------------------------------------
__global__ __launch_bounds__(256)
void split_rows(const float* __restrict__ src, __nv_bfloat16* __restrict__ hi,
                __nv_bfloat16* __restrict__ lo, int n4) {
    int i = blockIdx.x * 256 + threadIdx.x;
    if (i >= n4) return;
    float4 v = ((const float4*)src)[i];
    uint32_t h0, l0, h1, l1;
    split2(v.x, v.y, h0, l0);
    split2(v.z, v.w, h1, l1);
    ((uint32_t*)hi)[i * 2 + 0] = h0;
    ((uint32_t*)hi)[i * 2 + 1] = h1;
    ((uint32_t*)lo)[i * 2 + 0] = l0;
    ((uint32_t*)lo)[i * 2 + 1] = l1;
}

// ---------------------------------------------------------------------------
// transpose + split: W[1024(k)][1024(n)] fp32 -> WT[n][k] bf16 hi/lo
// ---------------------------------------------------------------------------
__global__ __launch_bounds__(256)
void transpose_split(const float* __restrict__ W, __nv_bfloat16* __restrict__ th,
                     __nv_bfloat16* __restrict__ tl) {
    __shared__ float s[32][33];
    const int n0 = blockIdx.x * 32, k0 = blockIdx.y * 32;
    const int tx = threadIdx.x, ty = threadIdx.y;  // 32 x 8
    #pragma unroll
    for (int i = 0; i < 4; i++)
        s[ty + 8 * i][tx] = W[(size_t)(k0 + ty + 8 * i) * 1024 + n0 + tx];
    __syncthreads();
    #pragma unroll
    for (int i = 0; i < 4; i++) {
        int n = ty + 8 * i;
        float v = s[tx][n];
        __nv_bfloat16 h = __float2bfloat16(v);
        __nv_bfloat16 l = __float2bfloat16(v - __bfloat162float(h));
        size_t o = (size_t)(n0 + n) * 1024 + k0 + tx;
        th[o] = h;
        tl[o] = l;
    }
}

// ---------------------------------------------------------------------------
// HMMA bf16x3 GEMM (R3-validated). Output: fp32 (Cf) or bf16 hi/lo (Chi/Clo).
// ---------------------------------------------------------------------------
#define GBUF 65536
#define GEMM_SMEM (2 * GBUF)

__global__ __launch_bounds__(256, 1)
void gemm_hmma(const __nv_bfloat16* __restrict__ Ahi,
               const __nv_bfloat16* __restrict__ Alo,
               const __nv_bfloat16* __restrict__ Bhi,
               const __nv_bfloat16* __restrict__ Blo,
               float* __restrict__ Cf,
               __nv_bfloat16* __restrict__ Chi,
               __nv_bfloat16* __restrict__ Clo) {
    extern __shared__ char smem[];
    const uint32_t sb = smem_u32(smem);
    const int tid = threadIdx.x, wid = tid >> 5, lane = tid & 31;
    const int bn = blockIdx.x * 128, bm = blockIdx.y * 128;
    const int warp_m = (wid & 1) * 64, warp_n = (wid >> 1) * 32;

    const uint4* Asrc[2] = {(const uint4*)(Ahi + (size_t)bm * 1024),
                            (const uint4*)(Alo + (size_t)bm * 1024)};
    const uint4* Bsrc[2] = {(const uint4*)(Bhi + (size_t)bn * 1024),
                            (const uint4*)(Blo + (size_t)bn * 1024)};

    const int lrow = tid >> 3, lcol = tid & 7;
    const uint32_t ldst = sw128(lrow * 128 + lcol * 16);

    float acc[4][4][4];
    #pragma unroll
    for (int i = 0; i < 4; i++)
        #pragma unroll
        for (int j = 0; j < 4; j++)
            #pragma unroll
            for (int r = 0; r < 4; r++) acc[i][j][r] = 0.f;

    const int arow = warp_m + (lane & 15);
    const int acb = (lane >> 4) << 4;
    const int brow = warp_n + ((lane >> 4) & 1) * 8 + (lane & 7);
    const int bcb = ((lane >> 3) & 1) * 16;

    auto load_chunk = [&](int c) {
        const uint32_t base = sb + (c & 1) * GBUF;
        const int kc8 = c * 8;
        #pragma unroll
        for (int pr = 0; pr < 2; pr++)
            #pragma unroll
            for (int p = 0; p < 4; p++)
                cpasync16(base + pr * 16384 + (ldst + p * 4096),
                          Asrc[pr] + (size_t)(lrow + p * 32) * 128 + kc8 + lcol);
        #pragma unroll
        for (int pr = 0; pr < 2; pr++)
            #pragma unroll
            for (int p = 0; p < 4; p++)
                cpasync16(base + 32768 + pr * 16384 + (ldst + p * 4096),
                          Bsrc[pr] + (size_t)(lrow + p * 32) * 128 + kc8 + lcol);
        CP_COMMIT();
    };

    load_chunk(0);
    for (int c = 0; c < 16; c++) {
        if (c + 1 < 16) { load_chunk(c + 1); CP_WAIT1(); }
        else CP_WAIT0();
        __syncthreads();

        const uint32_t base = sb + (c & 1) * GBUF;
        #pragma unroll
        for (int k16 = 0; k16 < 4; k16++) {
            uint32_t a_hi[4][4], a_lo[4][4], b_hi[2][4], b_lo[2][4];
            const int acolb = k16 * 32 + acb;
            const int bcolb = k16 * 32 + bcb;
            #pragma unroll
            for (int mi = 0; mi < 4; mi++) {
                uint32_t off = (uint32_t)(arow + mi * 16) * 128 + acolb;
                ldsm4(a_hi[mi], base + sw128(off));
                ldsm4(a_lo[mi], base + 16384 + sw128(off));
            }
            #pragma unroll
            for (int nh = 0; nh < 2; nh++) {
                uint32_t off = (uint32_t)(brow + nh * 16) * 128 + bcolb;
                ldsm4(b_hi[nh], base + 32768 + sw128(off));
                ldsm4(b_lo[nh], base + 49152 + sw128(off));
            }
            #pragma unroll
            for (int mi = 0; mi < 4; mi++)
                #pragma unroll
                for (int ni = 0; ni < 4; ni++) {
                    const uint32_t* bh = &b_hi[ni >> 1][(ni & 1) * 2];
                    const uint32_t* bl = &b_lo[ni >> 1][(ni & 1) * 2];
                    mma16816(acc[mi][ni], a_hi[mi], bh);
                    mma16816(acc[mi][ni], a_hi[mi], bl);
                    mma16816(acc[mi][ni], a_lo[mi], bh);
                }
        }
        __syncthreads();
    }

    #pragma unroll
    for (int mi = 0; mi < 4; mi++) {
        const int r0 = bm + warp_m + mi * 16 + (lane >> 2);
        #pragma unroll
        for (int ni = 0; ni < 4; ni++) {
            const int c0 = bn + warp_n + ni * 8 + (lane & 3) * 2;
            if (Cf) {
                *(float2*)(Cf + (size_t)r0 * 1024 + c0) =
                    make_float2(acc[mi][ni][0], acc[mi][ni][1]);
                *(float2*)(Cf + (size_t)(r0 + 8) * 1024 + c0) =
                    make_float2(acc[mi][ni][2], acc[mi][ni][3]);
            } else {
                uint32_t hi, lo;
                split2(acc[mi][ni][0], acc[mi][ni][1], hi, lo);
                *(uint32_t*)(Chi + (size_t)r0 * 1024 + c0) = hi;
                *(uint32_t*)(Clo + (size_t)r0 * 1024 + c0) = lo;
                split2(acc[mi][ni][2], acc[mi][ni][3], hi, lo);
                *(uint32_t*)(Chi + (size_t)(r0 + 8) * 1024 + c0) = hi;
                *(uint32_t*)(Clo + (size_t)(r0 + 8) * 1024 + c0) = lo;
            }
        }
    }
}

// ---------------------------------------------------------------------------
// HMMA flash attention, bf16x3.
//   CTA: 128 q rows x one head x one batch; 8 warps (16 q rows each).
//   KV tile 64, double-buffered cp.async. P stays in registers (C->A reuse).
//   smem: Qhi 16K | Qlo 16K | 2 x (Khi 8K|Klo 8K|Vhi 8K|Vlo 8K) | mask 256B
// ---------------------------------------------------------------------------
#define ATT_SMEM (32768 + 65536 + 256)

__global__ __launch_bounds__(256, 1)
void attn_hmma(const __nv_bfloat16* __restrict__ Qhi,
               const __nv_bfloat16* __restrict__ Qlo,
               const __nv_bfloat16* __restrict__ Khi,
               const __nv_bfloat16* __restrict__ Klo,
               const __nv_bfloat16* __restrict__ Vhi,
               const __nv_bfloat16* __restrict__ Vlo,
               const int* __restrict__ mask,
               __nv_bfloat16* __restrict__ Chi,
               __nv_bfloat16* __restrict__ Clo) {
    extern __shared__ char smem[];
    const uint32_t sb = smem_u32(smem);
    const int tid = threadIdx.x, wid = tid >> 5, lane = tid & 31;
    const int h = blockIdx.y, b = blockIdx.z;
    const int q0 = blockIdx.x * 128;

    const uint32_t sQ = 0;
    const uint32_t sKV = 32768;
    const uint32_t sM = 98304;

    const size_t hd = (size_t)h * 64;
    const __nv_bfloat16* Qh = Qhi + ((size_t)b * 2048 + q0) * 1024 + hd;
    const __nv_bfloat16* Ql = Qlo + ((size_t)b * 2048 + q0) * 1024 + hd;
    const __nv_bfloat16* Kh = Khi + (size_t)b * 2048 * 1024 + hd;
    const __nv_bfloat16* Kl = Klo + (size_t)b * 2048 * 1024 + hd;
    const __nv_bfloat16* Vh = Vhi + (size_t)b * 2048 * 1024 + hd;
    const __nv_bfloat16* Vl = Vlo + (size_t)b * 2048 * 1024 + hd;

    // Q tile: 128 rows x 8 granules x 2 arrays, 256 threads -> 4 passes each
    #pragma unroll
    for (int p = 0; p < 4; p++) {
        int g = tid + p * 256;
        int row = g >> 3, col = g & 7;
        uint32_t d = sw128(row * 128 + col * 16);
        cpasync16(sb + sQ + d, Qh + (size_t)row * 1024 + col * 8);
        cpasync16(sb + sQ + 16384 + d, Ql + (size_t)row * 1024 + col * 8);
    }
    CP_COMMIT();

    auto load_tile = [&](int t) {
        const uint32_t base = sb + sKV + (t & 1) * 32768;
        const int kv0 = t * 64;
        #pragma unroll
        for (int p = 0; p < 2; p++) {
            int g = tid + p * 256;
            int row = g >> 3, col = g & 7;
            uint32_t d = sw128(row * 128 + col * 16);
            size_t so = (size_t)(kv0 + row) * 1024 + col * 8;
            cpasync16(base + d, Kh + so);
            cpasync16(base + 8192 + d, Kl + so);
            cpasync16(base + 16384 + d, Vh + so);
            cpasync16(base + 24576 + d, Vl + so);
        }
        CP_COMMIT();
    };

    // fragment address components
    const int qrow = 16 * wid + (lane & 15);
    const uint32_t qcb = (lane >> 4) * 16;
    const int krow = ((lane >> 4) & 1) * 8 + (lane & 7);
    const uint32_t kcb = ((lane >> 3) & 1) * 16;
    const int vrow = (lane & 7) + ((lane >> 3) & 1) * 8;
    const uint32_t vcb = ((lane >> 4) & 1) * 16;
    const int cb = (lane & 3) * 2;

    float m0 = -FLT_MAX_, m1 = -FLT_MAX_, l0 = 0.f, l1 = 0.f;
    float o[8][4];
    #pragma unroll
    for (int i = 0; i < 8; i++)
        #pragma unroll
        for (int j = 0; j < 4; j++) o[i][j] = 0.f;

    uint32_t qh[4][4], ql[4][4];  // Q fragments, hoisted (loaded at t==0)

    load_tile(0);
    for (int t = 0; t < 32; t++) {
        if (t < 31) load_tile(t + 1);
        if (tid < 64) ((int*)(smem + sM))[tid] = mask[b * 2048 + t * 64 + tid];
        if (t < 31) CP_WAIT1(); else CP_WAIT0();
        __syncthreads();

        if (t == 0) {
            #pragma unroll
            for (int k16 = 0; k16 < 4; k16++) {
                uint32_t off = sw128((uint32_t)qrow * 128 + k16 * 32 + qcb);
                ldsm4(qh[k16], sb + sQ + off);
                ldsm4(ql[k16], sb + sQ + 16384 + off);
            }
        }

        const uint32_t kb = sb + sKV + (t & 1) * 32768;
        const uint32_t vb = kb + 16384;

        // S = Q K^T (bf16x3)
        float s[8][4];
        #pragma unroll
        for (int i = 0; i < 8; i++)
            #pragma unroll
            for (int j = 0; j < 4; j++) s[i][j] = 0.f;

        #pragma unroll
        for (int k16 = 0; k16 < 4; k16++) {
            #pragma unroll
            for (int nb = 0; nb < 4; nb++) {
                uint32_t kh4[4], kl4[4];
                uint32_t off = sw128((uint32_t)(nb * 16 + krow) * 128 + k16 * 32 + kcb);
                ldsm4(kh4, kb + off);
                ldsm4(kl4, kb + 8192 + off);
                mma16816(s[2 * nb], qh[k16], kh4);
                mma16816(s[2 * nb], qh[k16], kl4);
                mma16816(s[2 * nb], ql[k16], kh4);
                mma16816(s[2 * nb + 1], qh[k16], kh4 + 2);
                mma16816(s[2 * nb + 1], qh[k16], kl4 + 2);
                mma16816(s[2 * nb + 1], ql[k16], kh4 + 2);
            }
        }

        // scale -> clip -> mask -> online softmax
        const int* mk = (const int*)(smem + sM);
        float rm0 = -FLT_MAX_, rm1 = -FLT_MAX_;
        #pragma unroll
        for (int nt = 0; nt < 8; nt++) {
            int ma = mk[8 * nt + cb], mb_ = mk[8 * nt + cb + 1];
            float v;
            v = fminf(fmaxf(s[nt][0] * 0.125f, -10000.f), 10000.f);
            s[nt][0] = ma ? v : -FLT_MAX_;
            v = fminf(fmaxf(s[nt][1] * 0.125f, -10000.f), 10000.f);
            s[nt][1] = mb_ ? v : -FLT_MAX_;
            v = fminf(fmaxf(s[nt][2] * 0.125f, -10000.f), 10000.f);
            s[nt][2] = ma ? v : -FLT_MAX_;
            v = fminf(fmaxf(s[nt][3] * 0.125f, -10000.f), 10000.f);
            s[nt][3] = mb_ ? v : -FLT_MAX_;
            rm0 = fmaxf(rm0, fmaxf(s[nt][0], s[nt][1]));
            rm1 = fmaxf(rm1, fmaxf(s[nt][2], s[nt][3]));
        }
        rm0 = fmaxf(rm0, __shfl_xor_sync(0xffffffffu, rm0, 1));
        rm0 = fmaxf(rm0, __shfl_xor_sync(0xffffffffu, rm0, 2));
        rm1 = fmaxf(rm1, __shfl_xor_sync(0xffffffffu, rm1, 1));
        rm1 = fmaxf(rm1, __shfl_xor_sync(0xffffffffu, rm1, 2));

        float mn0 = fmaxf(m0, rm0), mn1 = fmaxf(m1, rm1);
        float a0 = __expf(m0 - mn0), a1 = __expf(m1 - mn1);
        float rs0 = 0.f, rs1 = 0.f;
        #pragma unroll
        for (int nt = 0; nt < 8; nt++) {
            s[nt][0] = __expf(s[nt][0] - mn0);
            s[nt][1] = __expf(s[nt][1] - mn0);
            s[nt][2] = __expf(s[nt][2] - mn1);
            s[nt][3] = __expf(s[nt][3] - mn1);
            rs0 += s[nt][0] + s[nt][1];
            rs1 += s[nt][2] + s[nt][3];
        }
        rs0 += __shfl_xor_sync(0xffffffffu, rs0, 1);
        rs0 += __shfl_xor_sync(0xffffffffu, rs0, 2);
        rs1 += __shfl_xor_sync(0xffffffffu, rs1, 1);
        rs1 += __shfl_xor_sync(0xffffffffu, rs1, 2);
        m0 = mn0; m1 = mn1;
        l0 = l0 * a0 + rs0; l1 = l1 * a1 + rs1;
        #pragma unroll
        for (int dt = 0; dt < 8; dt++) {
            o[dt][0] *= a0; o[dt][1] *= a0;
            o[dt][2] *= a1; o[dt][3] *= a1;
        }

        // O += P V  (P from registers via C->A fragment reuse, bf16x3)
        #pragma unroll
        for (int c = 0; c < 4; c++) {
            uint32_t ahi[4], alo[4];
            split2(s[2 * c][0], s[2 * c][1], ahi[0], alo[0]);
            split2(s[2 * c][2], s[2 * c][3], ahi[1], alo[1]);
            split2(s[2 * c + 1][0], s[2 * c + 1][1], ahi[2], alo[2]);
            split2(s[2 * c + 1][2], s[2 * c + 1][3], ahi[3], alo[3]);
            #pragma unroll
            for (int db = 0; db < 4; db++) {
                uint32_t vh4[4], vl4[4];
                uint32_t off = sw128((uint32_t)(c * 16 + vrow) * 128 + db * 32 + vcb);
                ldsm4t(vh4, vb + off);
                ldsm4t(vl4, vb + 8192 + off);
                mma16816(o[2 * db], ahi, vh4);
                mma16816(o[2 * db], ahi, vl4);
                mma16816(o[2 * db], alo, vh4);
                mma16816(o[2 * db + 1], ahi, vh4 + 2);
                mma16816(o[2 * db + 1], ahi, vl4 + 2);
                mma16816(o[2 * db + 1], alo, vh4 + 2);
            }
        }
        __syncthreads();
    }

    // normalize, split, store ctx (bf16 hi/lo), layout [b*2048+s][h*64+d]
    const float i0 = 1.f / l0, i1 = 1.f / l1;
    const size_t r0 = (size_t)b * 2048 + q0 + 16 * wid + (lane >> 2);
    #pragma unroll
    for (int dt = 0; dt < 8; dt++) {
        size_t col = hd + 8 * dt + cb;
        uint32_t hi, lo;
        split2(o[dt][0] * i0, o[dt][1] * i0, hi, lo);
        *(uint32_t*)(Chi + r0 * 1024 + col) = hi;
        *(uint32_t*)(Clo + r0 * 1024 + col) = lo;
        split2(o[dt][2] * i1, o[dt][3] * i1, hi, lo);
        *(uint32_t*)(Chi + (r0 + 8) * 1024 + col) = hi;
        *(uint32_t*)(Clo + (r0 + 8) * 1024 + col) = lo;
    }
}

// ---------------------------------------------------------------------------
extern "C" void kernel_launch(void* const* d_in, const int* in_sizes, int n_in,
                              void* d_out, int out_size) {
    const float* X    = (const float*)d_in[0];
    const int*   mask = (const int*)d_in[1];
    const float* W_Q  = (const float*)d_in[2];
    const float* W_K  = (const float*)d_in[3];
    const float* W_V  = (const float*)d_in[4];
    const float* W_O  = (const float*)d_in[5];
    float* out = (float*)d_out;

    __nv_bfloat16 *ahi, *alo, *wth, *wtl, *qhi, *qlo, *khi, *klo, *vhi, *vlo;
    cudaGetSymbolAddress((void**)&ahi, g_Ahi);
    cudaGetSymbolAddress((void**)&alo, g_Alo);
    cudaGetSymbolAddress((void**)&wth, g_WThi);
    cudaGetSymbolAddress((void**)&wtl, g_WTlo);
    cudaGetSymbolAddress((void**)&qhi, g_Qhi);
    cudaGetSymbolAddress((void**)&qlo, g_Qlo);
    cudaGetSymbolAddress((void**)&khi, g_Khi);
    cudaGetSymbolAddress((void**)&klo, g_Klo);
    cudaGetSymbolAddress((void**)&vhi, g_Vhi);
    cudaGetSymbolAddress((void**)&vlo, g_Vlo);

    cudaFuncSetAttribute(gemm_hmma, cudaFuncAttributeMaxDynamicSharedMemorySize,
                         GEMM_SMEM);
    cudaFuncSetAttribute(attn_hmma, cudaFuncAttributeMaxDynamicSharedMemorySize,
                         ATT_SMEM);

    const int n4 = 4096 * 1024 / 4;
    dim3 gt(32, 32), bt(32, 8);
    dim3 gg(1024 / 128, 4096 / 128);

    // X -> hi/lo
    split_rows<<<n4 / 256, 256>>>(X, ahi, alo, n4);

    // projections: write bf16 hi/lo directly
    transpose_split<<<gt, bt>>>(W_Q, wth, wtl);
    gemm_hmma<<<gg, 256, GEMM_SMEM>>>(ahi, alo, wth, wtl, nullptr, qhi, qlo);
    transpose_split<<<gt, bt>>>(W_K, wth, wtl);
    gemm_hmma<<<gg, 256, GEMM_SMEM>>>(ahi, alo, wth, wtl, nullptr, khi, klo);
    transpose_split<<<gt, bt>>>(W_V, wth, wtl);
    gemm_hmma<<<gg, 256, GEMM_SMEM>>>(ahi, alo, wth, wtl, nullptr, vhi, vlo);

    // attention: ctx hi/lo overwrites X split (no longer needed)
    dim3 ga(16, 16, 2);
    attn_hmma<<<ga, 256, ATT_SMEM>>>(qhi, qlo, khi, klo, vhi, vlo, mask,
                                     ahi, alo);

    // output projection: fp32 out
    transpose_split<<<gt, bt>>>(W_O, wth, wtl);
    gemm_hmma<<<gg, 256, GEMM_SMEM>>>(ahi, alo, wth, wtl, out, nullptr, nullptr);
}